// round 16
// baseline (speedup 1.0000x reference)
#include <cuda_runtime.h>
#include <cstddef>
#include <cstdint>

#define NN 100000
#define DD 128

__device__ float g_agg[(size_t)NN * DD];   // layer-1 neighbor sums
__device__ float g_q0 [NN], g_q1 [NN];     // x1·u0, x1·u1
__device__ float g_xv0[NN], g_xv1[NN];     // x1·v0, x1·v1
__device__ float g_aq0[NN], g_aq1[NN];     // scattered q sums
__device__ float g_r0 [NN], g_r1 [NN];
__device__ float g_inv[NN];
__device__ int   g_cnt[NN];
__device__ float g_u0[DD], g_u1[DD], g_v0[DD], g_v1[DD];
__device__ float g_c;

// ---------------------------------------------------------------------------
__global__ void inv_kernel(int n) {
    int i = blockIdx.x * blockDim.x + threadIdx.x;
    if (i < n) {
        g_inv[i] = 1.0f / fmaxf((float)g_cnt[i], 1.0f);
        g_aq0[i] = 0.f;
        g_aq1[i] = 0.f;
    }
}

// ---------------------------------------------------------------------------
// Scatter, 8 edges per warp (MLP-batched), degree counting folded in.
// ---------------------------------------------------------------------------
#define EPW 8
__global__ void scatter_kernel(const float* __restrict__ x,
                               const int* __restrict__ src,
                               const int* __restrict__ dst, int e) {
    int w    = (blockIdx.x * blockDim.x + threadIdx.x) >> 5;
    int lane = threadIdx.x & 31;
    int e0   = w * EPW;
    if (e0 >= e) return;
    int ne = min(EPW, e - e0);

    int s[EPW], d[EPW];
    #pragma unroll
    for (int i = 0; i < EPW; i++) {
        int idx = min(e0 + i, e - 1);
        s[i] = __ldg(src + idx);
        d[i] = __ldg(dst + idx);
    }
    float4 v[EPW];
    #pragma unroll
    for (int i = 0; i < EPW; i++)
        v[i] = *(const float4*)(x + (size_t)s[i] * DD + lane * 4);
    if (lane == 0) {
        #pragma unroll
        for (int i = 0; i < EPW; i++)
            if (i < ne) atomicAdd(&g_cnt[d[i]], 1);
    }
    #pragma unroll
    for (int i = 0; i < EPW; i++)
        if (i < ne)
            atomicAdd((float4*)(g_agg + (size_t)d[i] * DD + lane * 4), v[i]);
}

// ---------------------------------------------------------------------------
__global__ void scatter2_kernel(const int* __restrict__ src,
                                const int* __restrict__ dst, int e) {
    int i = blockIdx.x * blockDim.x + threadIdx.x;
    if (i >= e) return;
    int s = __ldg(src + i);
    int d = __ldg(dst + i);
    atomicAdd(&g_aq0[d], g_q0[s]);
    atomicAdd(&g_aq1[d], g_q1[s]);
}

// ---------------------------------------------------------------------------
// u/v projections, one warp per output row.
// ---------------------------------------------------------------------------
__global__ void uv_kernel(const float* __restrict__ W2l,
                          const float* __restrict__ W2r,
                          const float* __restrict__ b2,
                          const float* __restrict__ Wlin,
                          const float* __restrict__ blin) {
    int w    = (blockIdx.x * blockDim.x + threadIdx.x) >> 5;
    int lane = threadIdx.x & 31;
    if (w >= DD) return;
    const float* rl = W2l + (size_t)w * DD;
    const float* rr = W2r + (size_t)w * DD;
    float u0 = 0.f, u1 = 0.f, v0 = 0.f, v1 = 0.f;
    #pragma unroll
    for (int jj = 0; jj < 4; jj++) {
        int j = lane + 32 * jj;
        float a  = __ldg(rl + j);
        float b  = __ldg(rr + j);
        float w0 = __ldg(Wlin + j);
        float w1 = __ldg(Wlin + DD + j);
        u0 = fmaf(a, w0, u0);
        u1 = fmaf(a, w1, u1);
        v0 = fmaf(b, w0, v0);
        v1 = fmaf(b, w1, v1);
    }
    #pragma unroll
    for (int o = 16; o > 0; o >>= 1) {
        u0 += __shfl_down_sync(0xFFFFFFFFu, u0, o);
        u1 += __shfl_down_sync(0xFFFFFFFFu, u1, o);
        v0 += __shfl_down_sync(0xFFFFFFFFu, v0, o);
        v1 += __shfl_down_sync(0xFFFFFFFFu, v1, o);
    }
    if (lane == 0) {
        g_u0[w] = u0; g_u1[w] = u1; g_v0[w] = v0; g_v1[w] = v1;
    }
    if (w == 0) {
        float c = 0.f;
        #pragma unroll
        for (int jj = 0; jj < 4; jj++) {
            int j = lane + 32 * jj;
            c = fmaf(__ldg(b2 + j), __ldg(Wlin + j) + __ldg(Wlin + DD + j), c);
        }
        #pragma unroll
        for (int o = 16; o > 0; o >>= 1)
            c += __shfl_down_sync(0xFFFFFFFFu, c, o);
        if (lane == 0) g_c = c + __ldg(blin);
    }
}

// ---------------------------------------------------------------------------
// bf16-split tensor-core GEMM (mma.sync m16n8k16) fused with projection.
// A-staging uses prefetch.global.L2 issued one MMA phase ahead; staging loads
// are short-lived bursts hitting L2, keeping registers free during MMA.
// ---------------------------------------------------------------------------
#define GT 512
#define SM_WHI 0                   // [256][136] bf16 = 69632
#define SM_WLO 69632
#define SM_AHI 139264              // [128][136] bf16 = 34816
#define SM_ALO 174080
#define SM_PART 208896             // float[4][128][4] = 8192
#define SM_BIAS 217088             // 512
#define SM_PROJ 217600             // 4 x 512
#define SMEM_TOTAL 219648

__device__ __forceinline__ uint32_t smem_u32(const void* p) {
    uint32_t a;
    asm("{ .reg .u64 t; cvta.to.shared.u64 t, %1; cvt.u32.u64 %0, t; }"
        : "=r"(a) : "l"(p));
    return a;
}

__device__ __forceinline__ void prefetch_l2(const void* p) {
    asm volatile("prefetch.global.L2 [%0];" :: "l"(p));
}

__device__ __forceinline__ void split2(float a, float b,
                                       uint32_t& hi2, uint32_t& lo2) {
    uint32_t ia = __float_as_uint(a) & 0xFFFF0000u;
    uint32_t ib = __float_as_uint(b) & 0xFFFF0000u;
    hi2 = (ia >> 16) | ib;
    float la = a - __uint_as_float(ia);
    float lb = b - __uint_as_float(ib);
    asm("cvt.rn.bf16x2.f32 %0, %1, %2;" : "=r"(lo2) : "f"(lb), "f"(la));
}

__device__ __forceinline__ void ldsm_x4(uint32_t* r, uint32_t addr) {
    asm volatile("ldmatrix.sync.aligned.m8n8.x4.shared.b16 {%0,%1,%2,%3}, [%4];"
        : "=r"(r[0]), "=r"(r[1]), "=r"(r[2]), "=r"(r[3]) : "r"(addr));
}

__device__ __forceinline__ void ldsm_x2t(uint32_t* r, uint32_t addr) {
    asm volatile("ldmatrix.sync.aligned.m8n8.x2.trans.shared.b16 {%0,%1}, [%2];"
        : "=r"(r[0]), "=r"(r[1]) : "r"(addr));
}

__device__ __forceinline__ void mma_bf16(float* d, const uint32_t* a,
                                         const uint32_t* b) {
    asm volatile("mma.sync.aligned.m16n8k16.row.col.f32.bf16.bf16.f32 "
        "{%0,%1,%2,%3}, {%4,%5,%6,%7}, {%8,%9}, {%0,%1,%2,%3};"
        : "+f"(d[0]), "+f"(d[1]), "+f"(d[2]), "+f"(d[3])
        : "r"(a[0]), "r"(a[1]), "r"(a[2]), "r"(a[3]), "r"(b[0]), "r"(b[1]));
}

__global__ __launch_bounds__(GT, 1)
void sage_gemm_mma(const float* __restrict__ agg,
                   const float* __restrict__ xin,
                   const float* __restrict__ Wl,
                   const float* __restrict__ bias,
                   const float* __restrict__ Wr,
                   int n) {
    extern __shared__ char smem[];
    const uint32_t sb = smem_u32(smem);
    const int tid  = threadIdx.x;
    const int lane = tid & 31;
    const int wid  = tid >> 5;
    const int mi   = wid >> 2;
    const int ni   = wid & 3;
    const int c4   = tid & 31;   // staging column group
    const int rw   = tid >> 5;   // staging base row

    const int ntiles = (n + 127) >> 7;

    // Early prefetch of first tile's agg rows (overlaps W staging).
    if (blockIdx.x < ntiles) {
        const int base = blockIdx.x << 7;
        #pragma unroll
        for (int j = 0; j < 8; j++) {
            int grc = min(base + rw + 16 * j, n - 1);
            prefetch_l2(agg + (size_t)grc * DD + c4 * 4);
        }
    }

    // Stage W_cat = [W1l ; W1r] as bf16 hi/lo.
    for (int i = tid; i < 256 * 32; i += GT) {
        int row = i >> 5, cc = i & 31;
        const float* wsrc = (row < 128) ? (Wl + (size_t)row * 128)
                                        : (Wr + (size_t)(row - 128) * 128);
        float4 v = ((const float4*)wsrc)[cc];
        uint32_t h01, l01, h23, l23;
        split2(v.x, v.y, h01, l01);
        split2(v.z, v.w, h23, l23);
        *(uint2*)(smem + SM_WHI + row * 272 + cc * 8) = make_uint2(h01, h23);
        *(uint2*)(smem + SM_WLO + row * 272 + cc * 8) = make_uint2(l01, l23);
    }
    if (tid < DD) {
        ((float*)(smem + SM_BIAS))[tid]        = bias[tid];
        ((float*)(smem + SM_PROJ))[tid]        = g_u0[tid];
        ((float*)(smem + SM_PROJ + 512))[tid]  = g_u1[tid];
        ((float*)(smem + SM_PROJ + 1024))[tid] = g_v0[tid];
        ((float*)(smem + SM_PROJ + 1536))[tid] = g_v1[tid];
    }
    __syncthreads();

    for (int t = blockIdx.x; t < ntiles; t += gridDim.x) {
        const int base = t << 7;

        float D[2][4][4];
        #pragma unroll
        for (int mt = 0; mt < 2; mt++)
            #pragma unroll
            for (int nt = 0; nt < 4; nt++)
                #pragma unroll
                for (int j = 0; j < 4; j++) D[mt][nt][j] = 0.f;

        // ---- stage h0: burst-load agg (L2-warm), scale, split, store ----
        {
            float4 vb[8];
            float  iv[8];
            #pragma unroll
            for (int j = 0; j < 8; j++) {
                int grc = min(base + rw + 16 * j, n - 1);
                vb[j] = ((const float4*)(agg + (size_t)grc * DD))[c4];
                iv[j] = g_inv[grc];
            }
            #pragma unroll
            for (int j = 0; j < 8; j++) {
                int row = rw + 16 * j;
                uint32_t h01, l01, h23, l23;
                split2(vb[j].x * iv[j], vb[j].y * iv[j], h01, l01);
                split2(vb[j].z * iv[j], vb[j].w * iv[j], h23, l23);
                *(uint2*)(smem + SM_AHI + row * 272 + c4 * 8) = make_uint2(h01, h23);
                *(uint2*)(smem + SM_ALO + row * 272 + c4 * 8) = make_uint2(l01, l23);
            }
        }
        __syncthreads();

        // ---- prefetch h1 (emb) into L2; consumed next phase ----
        #pragma unroll
        for (int j = 0; j < 8; j++) {
            int grc = min(base + rw + 16 * j, n - 1);
            prefetch_l2(xin + (size_t)grc * DD + c4 * 4);
        }

        // ---- mma over h0 ----
        #pragma unroll
        for (int ks = 0; ks < 8; ks++) {
            const int kb = ks * 16;
            uint32_t bh[4][2], bl[4][2];
            uint32_t bko = (kb + (lane & 15)) * 272;
            #pragma unroll
            for (int nt = 0; nt < 4; nt++) {
                uint32_t cb2 = (ni * 32 + nt * 8) * 2;
                ldsm_x2t(bh[nt], sb + SM_WHI + bko + cb2);
                ldsm_x2t(bl[nt], sb + SM_WLO + bko + cb2);
            }
            uint32_t ah[2][4], al[2][4];
            uint32_t arow = (lane & 7) + ((lane >> 3) & 1) * 8;
            uint32_t akc  = kb + (lane >> 4) * 8;
            #pragma unroll
            for (int mt = 0; mt < 2; mt++) {
                uint32_t off = (mi * 32 + mt * 16 + arow) * 272 + akc * 2;
                ldsm_x4(ah[mt], sb + SM_AHI + off);
                ldsm_x4(al[mt], sb + SM_ALO + off);
            }
            #pragma unroll
            for (int mt = 0; mt < 2; mt++)
                #pragma unroll
                for (int nt = 0; nt < 4; nt++) {
                    mma_bf16(D[mt][nt], ah[mt], bh[nt]);
                    mma_bf16(D[mt][nt], ah[mt], bl[nt]);
                    mma_bf16(D[mt][nt], al[mt], bh[nt]);
                }
        }
        __syncthreads();   // all warps done reading A(h0)

        // ---- stage h1: burst-load emb (L2-warm), split, store ----
        {
            float4 vb[8];
            #pragma unroll
            for (int j = 0; j < 8; j++) {
                int grc = min(base + rw + 16 * j, n - 1);
                vb[j] = ((const float4*)(xin + (size_t)grc * DD))[c4];
            }
            #pragma unroll
            for (int j = 0; j < 8; j++) {
                int row = rw + 16 * j;
                uint32_t h01, l01, h23, l23;
                split2(vb[j].x, vb[j].y, h01, l01);
                split2(vb[j].z, vb[j].w, h23, l23);
                *(uint2*)(smem + SM_AHI + row * 272 + c4 * 8) = make_uint2(h01, h23);
                *(uint2*)(smem + SM_ALO + row * 272 + c4 * 8) = make_uint2(l01, l23);
            }
        }
        __syncthreads();

        // ---- prefetch next tile h0 (agg) into L2 ----
        int tn = t + gridDim.x;
        if (tn < ntiles) {
            const int nb = tn << 7;
            #pragma unroll
            for (int j = 0; j < 8; j++) {
                int grc = min(nb + rw + 16 * j, n - 1);
                prefetch_l2(agg + (size_t)grc * DD + c4 * 4);
            }
        }

        // ---- mma over h1 ----
        #pragma unroll
        for (int ks = 0; ks < 8; ks++) {
            const int kb = ks * 16;
            uint32_t bh[4][2], bl[4][2];
            uint32_t bko = (128 + kb + (lane & 15)) * 272;
            #pragma unroll
            for (int nt = 0; nt < 4; nt++) {
                uint32_t cb2 = (ni * 32 + nt * 8) * 2;
                ldsm_x2t(bh[nt], sb + SM_WHI + bko + cb2);
                ldsm_x2t(bl[nt], sb + SM_WLO + bko + cb2);
            }
            uint32_t ah[2][4], al[2][4];
            uint32_t arow = (lane & 7) + ((lane >> 3) & 1) * 8;
            uint32_t akc  = kb + (lane >> 4) * 8;
            #pragma unroll
            for (int mt = 0; mt < 2; mt++) {
                uint32_t off = (mi * 32 + mt * 16 + arow) * 272 + akc * 2;
                ldsm_x4(ah[mt], sb + SM_AHI + off);
                ldsm_x4(al[mt], sb + SM_ALO + off);
            }
            #pragma unroll
            for (int mt = 0; mt < 2; mt++)
                #pragma unroll
                for (int nt = 0; nt < 4; nt++) {
                    mma_bf16(D[mt][nt], ah[mt], bh[nt]);
                    mma_bf16(D[mt][nt], ah[mt], bl[nt]);
                    mma_bf16(D[mt][nt], al[mt], bh[nt]);
                }
        }

        // ---- epilogue: relu+bias, project, reduce ----
        const float* bs  = (const float*)(smem + SM_BIAS);
        const float* pu0 = (const float*)(smem + SM_PROJ);
        const float* pu1 = (const float*)(smem + SM_PROJ + 512);
        const float* pv0 = (const float*)(smem + SM_PROJ + 1024);
        const float* pv1 = (const float*)(smem + SM_PROJ + 1536);
        float* part = (float*)(smem + SM_PART);
        const int g = lane >> 2, c = lane & 3;

        #pragma unroll
        for (int mt = 0; mt < 2; mt++) {
            float pl[4] = {0.f, 0.f, 0.f, 0.f};
            float ph[4] = {0.f, 0.f, 0.f, 0.f};
            #pragma unroll
            for (int nt = 0; nt < 4; nt++) {
                int col = ni * 32 + nt * 8 + 2 * c;
                float b0 = bs[col], b1 = bs[col + 1];
                float s00 = fmaxf(D[mt][nt][0] + b0, 0.f);
                float s01 = fmaxf(D[mt][nt][1] + b1, 0.f);
                float s10 = fmaxf(D[mt][nt][2] + b0, 0.f);
                float s11 = fmaxf(D[mt][nt][3] + b1, 0.f);
                float a0, a1;
                a0 = pu0[col]; a1 = pu0[col + 1];
                pl[0] += s00 * a0 + s01 * a1;  ph[0] += s10 * a0 + s11 * a1;
                a0 = pu1[col]; a1 = pu1[col + 1];
                pl[1] += s00 * a0 + s01 * a1;  ph[1] += s10 * a0 + s11 * a1;
                a0 = pv0[col]; a1 = pv0[col + 1];
                pl[2] += s00 * a0 + s01 * a1;  ph[2] += s10 * a0 + s11 * a1;
                a0 = pv1[col]; a1 = pv1[col + 1];
                pl[3] += s00 * a0 + s01 * a1;  ph[3] += s10 * a0 + s11 * a1;
            }
            #pragma unroll
            for (int o = 1; o <= 2; o <<= 1) {
                #pragma unroll
                for (int j = 0; j < 4; j++) {
                    pl[j] += __shfl_xor_sync(0xFFFFFFFFu, pl[j], o);
                    ph[j] += __shfl_xor_sync(0xFFFFFFFFu, ph[j], o);
                }
            }
            if (c == 0) {
                int rl = mi * 32 + mt * 16 + g;
                int rh = rl + 8;
                #pragma unroll
                for (int j = 0; j < 4; j++) {
                    part[j * 512 + rl * 4 + ni] = pl[j];
                    part[j * 512 + rh * 4 + ni] = ph[j];
                }
            }
        }
        __syncthreads();
        if (tid < 128) {
            int gr = base + tid;
            if (gr < n) {
                float s[4];
                #pragma unroll
                for (int j = 0; j < 4; j++) {
                    const float* p = part + j * 512 + tid * 4;
                    s[j] = p[0] + p[1] + p[2] + p[3];
                }
                g_q0 [gr] = s[0];
                g_q1 [gr] = s[1];
                g_xv0[gr] = s[2];
                g_xv1[gr] = s[3];
            }
        }
        __syncthreads();   // part reads done before next tile's epilogue
    }
}

// ---------------------------------------------------------------------------
__global__ void fold_kernel(int n) {
    int v = blockIdx.x * blockDim.x + threadIdx.x;
    if (v >= n) return;
    float inv = g_inv[v];
    g_r0[v] = fmaf(inv, g_aq0[v], g_xv0[v]);
    g_r1[v] = fmaf(inv, g_aq1[v], g_xv1[v]);
}

// ---------------------------------------------------------------------------
__global__ void predict_kernel(const int* __restrict__ s,
                               const int* __restrict__ d,
                               float* __restrict__ out, int L) {
    int l = blockIdx.x * blockDim.x + threadIdx.x;
    if (l >= L) return;
    out[l] = g_r0[__ldg(s + l)] + g_r1[__ldg(d + l)] + g_c;
}

// ---------------------------------------------------------------------------
extern "C" void kernel_launch(void* const* d_in, const int* in_sizes, int n_in,
                              void* d_out, int out_size) {
    const int*   ei   = (const int*)d_in[0];
    const int*   eli  = (const int*)d_in[1];
    const float* emb  = (const float*)d_in[2];
    const float* W1l  = (const float*)d_in[3];
    const float* b1   = (const float*)d_in[4];
    const float* W1r  = (const float*)d_in[5];
    const float* W2l  = (const float*)d_in[6];
    const float* b2   = (const float*)d_in[7];
    const float* W2r  = (const float*)d_in[8];
    const float* Wlin = (const float*)d_in[9];
    const float* blin = (const float*)d_in[10];
    float*       out  = (float*)d_out;

    const int E = in_sizes[0] / 2;
    const int L = in_sizes[1] / 2;
    const int N = in_sizes[2] / DD;

    const int* src = ei;
    const int* dst = ei + E;
    const int* ls  = eli;
    const int* ld  = eli + L;

    void* p_agg = nullptr; cudaGetSymbolAddress(&p_agg, g_agg);
    void* p_cnt = nullptr; cudaGetSymbolAddress(&p_cnt, g_cnt);
    float* agg = (float*)p_agg;

    cudaFuncSetAttribute(sage_gemm_mma,
                         cudaFuncAttributeMaxDynamicSharedMemorySize,
                         SMEM_TOTAL);

    const int nwarps = (E + EPW - 1) / EPW;
    const int scatter_blocks = ((size_t)nwarps * 32 + 255) / 256;

    // Setup
    cudaMemsetAsync(p_cnt, 0, sizeof(int) * (size_t)N);
    cudaMemsetAsync(p_agg, 0, sizeof(float) * (size_t)N * DD);
    uv_kernel<<<16, 256>>>(W2l, W2r, b2, Wlin, blin);

    // Layer 1 aggregation (with fused degree count) + tensor-core GEMM
    scatter_kernel<<<scatter_blocks, 256>>>(emb, src, dst, E);
    inv_kernel<<<(N + 255) / 256, 256>>>(N);
    sage_gemm_mma<<<148, GT, SMEM_TOTAL>>>(agg, emb, W1l, b1, W1r, N);

    // Layer 2: scalar scatter + fold + predict
    scatter2_kernel<<<(E + 255) / 256, 256>>>(src, dst, E);
    fold_kernel<<<(N + 255) / 256, 256>>>(N);
    predict_kernel<<<(L + 255) / 256, 256>>>(ls, ld, out, L);
}

// round 17
// speedup vs baseline: 1.0275x; 1.0275x over previous
#include <cuda_runtime.h>
#include <cstddef>
#include <cstdint>

#define NN 100000
#define DD 128

__device__ float g_agg[(size_t)NN * DD];   // layer-1 neighbor sums
__device__ float g_q0 [NN], g_q1 [NN];     // x1·u0, x1·u1
__device__ float g_xv0[NN], g_xv1[NN];     // x1·v0, x1·v1
__device__ float g_aq0[NN], g_aq1[NN];     // scattered q sums
__device__ float g_r0 [NN], g_r1 [NN];
__device__ float g_inv[NN];
__device__ int   g_cnt[NN];
__device__ float g_u0[DD], g_u1[DD], g_v0[DD], g_v1[DD];
__device__ float g_c;

// ---------------------------------------------------------------------------
__global__ void inv_kernel(int n) {
    int i = blockIdx.x * blockDim.x + threadIdx.x;
    if (i < n) {
        g_inv[i] = 1.0f / fmaxf((float)g_cnt[i], 1.0f);
        g_aq0[i] = 0.f;
        g_aq1[i] = 0.f;
    }
}

// ---------------------------------------------------------------------------
// Scatter, 4 edges per warp (measured-best config), degree counting folded in.
// ---------------------------------------------------------------------------
#define EPW 4
__global__ void scatter_kernel(const float* __restrict__ x,
                               const int* __restrict__ src,
                               const int* __restrict__ dst, int e) {
    int w    = (blockIdx.x * blockDim.x + threadIdx.x) >> 5;
    int lane = threadIdx.x & 31;
    int e0   = w * EPW;
    if (e0 >= e) return;
    int ne = min(EPW, e - e0);

    int s[EPW], d[EPW];
    #pragma unroll
    for (int i = 0; i < EPW; i++) {
        int idx = min(e0 + i, e - 1);
        s[i] = __ldg(src + idx);
        d[i] = __ldg(dst + idx);
    }
    float4 v[EPW];
    #pragma unroll
    for (int i = 0; i < EPW; i++)
        v[i] = *(const float4*)(x + (size_t)s[i] * DD + lane * 4);
    if (lane == 0) {
        #pragma unroll
        for (int i = 0; i < EPW; i++)
            if (i < ne) atomicAdd(&g_cnt[d[i]], 1);
    }
    #pragma unroll
    for (int i = 0; i < EPW; i++)
        if (i < ne)
            atomicAdd((float4*)(g_agg + (size_t)d[i] * DD + lane * 4), v[i]);
}

// ---------------------------------------------------------------------------
__global__ void scatter2_kernel(const int* __restrict__ src,
                                const int* __restrict__ dst, int e) {
    int i = blockIdx.x * blockDim.x + threadIdx.x;
    if (i >= e) return;
    int s = __ldg(src + i);
    int d = __ldg(dst + i);
    atomicAdd(&g_aq0[d], g_q0[s]);
    atomicAdd(&g_aq1[d], g_q1[s]);
}

// ---------------------------------------------------------------------------
// u/v projections, one warp per output row.
// ---------------------------------------------------------------------------
__global__ void uv_kernel(const float* __restrict__ W2l,
                          const float* __restrict__ W2r,
                          const float* __restrict__ b2,
                          const float* __restrict__ Wlin,
                          const float* __restrict__ blin) {
    int w    = (blockIdx.x * blockDim.x + threadIdx.x) >> 5;
    int lane = threadIdx.x & 31;
    if (w >= DD) return;
    const float* rl = W2l + (size_t)w * DD;
    const float* rr = W2r + (size_t)w * DD;
    float u0 = 0.f, u1 = 0.f, v0 = 0.f, v1 = 0.f;
    #pragma unroll
    for (int jj = 0; jj < 4; jj++) {
        int j = lane + 32 * jj;
        float a  = __ldg(rl + j);
        float b  = __ldg(rr + j);
        float w0 = __ldg(Wlin + j);
        float w1 = __ldg(Wlin + DD + j);
        u0 = fmaf(a, w0, u0);
        u1 = fmaf(a, w1, u1);
        v0 = fmaf(b, w0, v0);
        v1 = fmaf(b, w1, v1);
    }
    #pragma unroll
    for (int o = 16; o > 0; o >>= 1) {
        u0 += __shfl_down_sync(0xFFFFFFFFu, u0, o);
        u1 += __shfl_down_sync(0xFFFFFFFFu, u1, o);
        v0 += __shfl_down_sync(0xFFFFFFFFu, v0, o);
        v1 += __shfl_down_sync(0xFFFFFFFFu, v1, o);
    }
    if (lane == 0) {
        g_u0[w] = u0; g_u1[w] = u1; g_v0[w] = v0; g_v1[w] = v1;
    }
    if (w == 0) {
        float c = 0.f;
        #pragma unroll
        for (int jj = 0; jj < 4; jj++) {
            int j = lane + 32 * jj;
            c = fmaf(__ldg(b2 + j), __ldg(Wlin + j) + __ldg(Wlin + DD + j), c);
        }
        #pragma unroll
        for (int o = 16; o > 0; o >>= 1)
            c += __shfl_down_sync(0xFFFFFFFFu, c, o);
        if (lane == 0) g_c = c + __ldg(blin);
    }
}

// ---------------------------------------------------------------------------
// bf16-split tensor-core GEMM (mma.sync m16n8k16) fused with projection.
// 1024 threads / 32 warps (occ 50%): each warp owns a 16x32 output slice,
// halving per-warp register state so 8 warps/SMSP hide ldsm->mma latency.
// ---------------------------------------------------------------------------
#define GT 1024
#define SM_WHI 0                   // [256][136] bf16 = 69632
#define SM_WLO 69632
#define SM_AHI 139264              // [128][136] bf16 = 34816
#define SM_ALO 174080
#define SM_PART 208896             // float[4][128][4] = 8192
#define SM_BIAS 217088             // 512
#define SM_PROJ 217600             // 4 x 512
#define SMEM_TOTAL 219648

__device__ __forceinline__ uint32_t smem_u32(const void* p) {
    uint32_t a;
    asm("{ .reg .u64 t; cvta.to.shared.u64 t, %1; cvt.u32.u64 %0, t; }"
        : "=r"(a) : "l"(p));
    return a;
}

__device__ __forceinline__ void split2(float a, float b,
                                       uint32_t& hi2, uint32_t& lo2) {
    uint32_t ia = __float_as_uint(a) & 0xFFFF0000u;
    uint32_t ib = __float_as_uint(b) & 0xFFFF0000u;
    hi2 = (ia >> 16) | ib;
    float la = a - __uint_as_float(ia);
    float lb = b - __uint_as_float(ib);
    asm("cvt.rn.bf16x2.f32 %0, %1, %2;" : "=r"(lo2) : "f"(lb), "f"(la));
}

__device__ __forceinline__ void ldsm_x4(uint32_t* r, uint32_t addr) {
    asm volatile("ldmatrix.sync.aligned.m8n8.x4.shared.b16 {%0,%1,%2,%3}, [%4];"
        : "=r"(r[0]), "=r"(r[1]), "=r"(r[2]), "=r"(r[3]) : "r"(addr));
}

__device__ __forceinline__ void ldsm_x2t(uint32_t* r, uint32_t addr) {
    asm volatile("ldmatrix.sync.aligned.m8n8.x2.trans.shared.b16 {%0,%1}, [%2];"
        : "=r"(r[0]), "=r"(r[1]) : "r"(addr));
}

__device__ __forceinline__ void mma_bf16(float* d, const uint32_t* a,
                                         const uint32_t* b) {
    asm volatile("mma.sync.aligned.m16n8k16.row.col.f32.bf16.bf16.f32 "
        "{%0,%1,%2,%3}, {%4,%5,%6,%7}, {%8,%9}, {%0,%1,%2,%3};"
        : "+f"(d[0]), "+f"(d[1]), "+f"(d[2]), "+f"(d[3])
        : "r"(a[0]), "r"(a[1]), "r"(a[2]), "r"(a[3]), "r"(b[0]), "r"(b[1]));
}

__global__ __launch_bounds__(GT, 1)
void sage_gemm_mma(const float* __restrict__ agg,
                   const float* __restrict__ xin,
                   const float* __restrict__ Wl,
                   const float* __restrict__ bias,
                   const float* __restrict__ Wr,
                   int n) {
    extern __shared__ char smem[];
    const uint32_t sb = smem_u32(smem);
    const int tid  = threadIdx.x;
    const int lane = tid & 31;
    const int wid  = tid >> 5;
    const int mi   = wid >> 2;   // 0..7: rows mi*16 .. mi*16+15
    const int ni   = wid & 3;    // 0..3: cols ni*32 .. ni*32+31
    const int c4   = tid & 31;   // staging column group
    const int rw   = tid >> 5;   // staging base row (0..31)

    // Stage W_cat = [W1l ; W1r] as bf16 hi/lo.
    for (int i = tid; i < 256 * 32; i += GT) {
        int row = i >> 5, cc = i & 31;
        const float* wsrc = (row < 128) ? (Wl + (size_t)row * 128)
                                        : (Wr + (size_t)(row - 128) * 128);
        float4 v = ((const float4*)wsrc)[cc];
        uint32_t h01, l01, h23, l23;
        split2(v.x, v.y, h01, l01);
        split2(v.z, v.w, h23, l23);
        *(uint2*)(smem + SM_WHI + row * 272 + cc * 8) = make_uint2(h01, h23);
        *(uint2*)(smem + SM_WLO + row * 272 + cc * 8) = make_uint2(l01, l23);
    }
    if (tid < DD) {
        ((float*)(smem + SM_BIAS))[tid]        = bias[tid];
        ((float*)(smem + SM_PROJ))[tid]        = g_u0[tid];
        ((float*)(smem + SM_PROJ + 512))[tid]  = g_u1[tid];
        ((float*)(smem + SM_PROJ + 1024))[tid] = g_v0[tid];
        ((float*)(smem + SM_PROJ + 1536))[tid] = g_v1[tid];
    }
    __syncthreads();

    const int ntiles = (n + 127) >> 7;
    for (int t = blockIdx.x; t < ntiles; t += gridDim.x) {
        const int base = t << 7;

        float D[4][4];   // [nt][frag]
        #pragma unroll
        for (int nt = 0; nt < 4; nt++)
            #pragma unroll
            for (int j = 0; j < 4; j++) D[nt][j] = 0.f;

        #pragma unroll
        for (int h = 0; h < 2; h++) {
            __syncthreads();
            // Stage A half: each thread 4 rows (burst loads, then split/store)
            {
                float4 vb[4];
                float  iv[4];
                #pragma unroll
                for (int j = 0; j < 4; j++) {
                    int grc = min(base + rw + 32 * j, n - 1);
                    if (h == 0) {
                        vb[j] = ((const float4*)(agg + (size_t)grc * DD))[c4];
                        iv[j] = g_inv[grc];
                    } else {
                        vb[j] = ((const float4*)(xin + (size_t)grc * DD))[c4];
                        iv[j] = 1.f;
                    }
                }
                #pragma unroll
                for (int j = 0; j < 4; j++) {
                    int row = rw + 32 * j;
                    uint32_t h01, l01, h23, l23;
                    split2(vb[j].x * iv[j], vb[j].y * iv[j], h01, l01);
                    split2(vb[j].z * iv[j], vb[j].w * iv[j], h23, l23);
                    *(uint2*)(smem + SM_AHI + row * 272 + c4 * 8) = make_uint2(h01, h23);
                    *(uint2*)(smem + SM_ALO + row * 272 + c4 * 8) = make_uint2(l01, l23);
                }
            }
            __syncthreads();

            const uint32_t wrow0 = h * 128;
            #pragma unroll
            for (int ks = 0; ks < 8; ks++) {
                const int kb = ks * 16;
                uint32_t bh[4][2], bl[4][2];
                uint32_t bko = (wrow0 + kb + (lane & 15)) * 272;
                #pragma unroll
                for (int nt = 0; nt < 4; nt++) {
                    uint32_t cb2 = (ni * 32 + nt * 8) * 2;
                    ldsm_x2t(bh[nt], sb + SM_WHI + bko + cb2);
                    ldsm_x2t(bl[nt], sb + SM_WLO + bko + cb2);
                }
                uint32_t ah[4], al[4];
                uint32_t arow = (lane & 7) + ((lane >> 3) & 1) * 8;
                uint32_t akc  = kb + (lane >> 4) * 8;
                uint32_t off  = (mi * 16 + arow) * 272 + akc * 2;
                ldsm_x4(ah, sb + SM_AHI + off);
                ldsm_x4(al, sb + SM_ALO + off);
                #pragma unroll
                for (int nt = 0; nt < 4; nt++) {
                    mma_bf16(D[nt], ah, bh[nt]);
                    mma_bf16(D[nt], ah, bl[nt]);
                    mma_bf16(D[nt], al, bh[nt]);
                }
            }
        }

        // ---- epilogue: relu+bias, project, reduce ----
        const float* bs  = (const float*)(smem + SM_BIAS);
        const float* pu0 = (const float*)(smem + SM_PROJ);
        const float* pu1 = (const float*)(smem + SM_PROJ + 512);
        const float* pv0 = (const float*)(smem + SM_PROJ + 1024);
        const float* pv1 = (const float*)(smem + SM_PROJ + 1536);
        float* part = (float*)(smem + SM_PART);
        const int g = lane >> 2, c = lane & 3;

        {
            float pl[4] = {0.f, 0.f, 0.f, 0.f};
            float ph[4] = {0.f, 0.f, 0.f, 0.f};
            #pragma unroll
            for (int nt = 0; nt < 4; nt++) {
                int col = ni * 32 + nt * 8 + 2 * c;
                float b0 = bs[col], b1 = bs[col + 1];
                float s00 = fmaxf(D[nt][0] + b0, 0.f);
                float s01 = fmaxf(D[nt][1] + b1, 0.f);
                float s10 = fmaxf(D[nt][2] + b0, 0.f);
                float s11 = fmaxf(D[nt][3] + b1, 0.f);
                float a0, a1;
                a0 = pu0[col]; a1 = pu0[col + 1];
                pl[0] += s00 * a0 + s01 * a1;  ph[0] += s10 * a0 + s11 * a1;
                a0 = pu1[col]; a1 = pu1[col + 1];
                pl[1] += s00 * a0 + s01 * a1;  ph[1] += s10 * a0 + s11 * a1;
                a0 = pv0[col]; a1 = pv0[col + 1];
                pl[2] += s00 * a0 + s01 * a1;  ph[2] += s10 * a0 + s11 * a1;
                a0 = pv1[col]; a1 = pv1[col + 1];
                pl[3] += s00 * a0 + s01 * a1;  ph[3] += s10 * a0 + s11 * a1;
            }
            #pragma unroll
            for (int o = 1; o <= 2; o <<= 1) {
                #pragma unroll
                for (int j = 0; j < 4; j++) {
                    pl[j] += __shfl_xor_sync(0xFFFFFFFFu, pl[j], o);
                    ph[j] += __shfl_xor_sync(0xFFFFFFFFu, ph[j], o);
                }
            }
            if (c == 0) {
                int rl = mi * 16 + g;
                int rh = rl + 8;
                #pragma unroll
                for (int j = 0; j < 4; j++) {
                    part[j * 512 + rl * 4 + ni] = pl[j];
                    part[j * 512 + rh * 4 + ni] = ph[j];
                }
            }
        }
        __syncthreads();
        if (tid < 128) {
            int gr = base + tid;
            if (gr < n) {
                float s[4];
                #pragma unroll
                for (int j = 0; j < 4; j++) {
                    const float* p = part + j * 512 + tid * 4;
                    s[j] = p[0] + p[1] + p[2] + p[3];
                }
                g_q0 [gr] = s[0];
                g_q1 [gr] = s[1];
                g_xv0[gr] = s[2];
                g_xv1[gr] = s[3];
            }
        }
        __syncthreads();   // part reads done before next tile overwrites
    }
}

// ---------------------------------------------------------------------------
__global__ void fold_kernel(int n) {
    int v = blockIdx.x * blockDim.x + threadIdx.x;
    if (v >= n) return;
    float inv = g_inv[v];
    g_r0[v] = fmaf(inv, g_aq0[v], g_xv0[v]);
    g_r1[v] = fmaf(inv, g_aq1[v], g_xv1[v]);
}

// ---------------------------------------------------------------------------
__global__ void predict_kernel(const int* __restrict__ s,
                               const int* __restrict__ d,
                               float* __restrict__ out, int L) {
    int l = blockIdx.x * blockDim.x + threadIdx.x;
    if (l >= L) return;
    out[l] = g_r0[__ldg(s + l)] + g_r1[__ldg(d + l)] + g_c;
}

// ---------------------------------------------------------------------------
extern "C" void kernel_launch(void* const* d_in, const int* in_sizes, int n_in,
                              void* d_out, int out_size) {
    const int*   ei   = (const int*)d_in[0];
    const int*   eli  = (const int*)d_in[1];
    const float* emb  = (const float*)d_in[2];
    const float* W1l  = (const float*)d_in[3];
    const float* b1   = (const float*)d_in[4];
    const float* W1r  = (const float*)d_in[5];
    const float* W2l  = (const float*)d_in[6];
    const float* b2   = (const float*)d_in[7];
    const float* W2r  = (const float*)d_in[8];
    const float* Wlin = (const float*)d_in[9];
    const float* blin = (const float*)d_in[10];
    float*       out  = (float*)d_out;

    const int E = in_sizes[0] / 2;
    const int L = in_sizes[1] / 2;
    const int N = in_sizes[2] / DD;

    const int* src = ei;
    const int* dst = ei + E;
    const int* ls  = eli;
    const int* ld  = eli + L;

    void* p_agg = nullptr; cudaGetSymbolAddress(&p_agg, g_agg);
    void* p_cnt = nullptr; cudaGetSymbolAddress(&p_cnt, g_cnt);
    float* agg = (float*)p_agg;

    cudaFuncSetAttribute(sage_gemm_mma,
                         cudaFuncAttributeMaxDynamicSharedMemorySize,
                         SMEM_TOTAL);

    const int nwarps = (E + EPW - 1) / EPW;
    const int scatter_blocks = ((size_t)nwarps * 32 + 255) / 256;

    // Setup
    cudaMemsetAsync(p_cnt, 0, sizeof(int) * (size_t)N);
    cudaMemsetAsync(p_agg, 0, sizeof(float) * (size_t)N * DD);
    uv_kernel<<<16, 256>>>(W2l, W2r, b2, Wlin, blin);

    // Layer 1 aggregation (with fused degree count) + tensor-core GEMM
    scatter_kernel<<<scatter_blocks, 256>>>(emb, src, dst, E);
    inv_kernel<<<(N + 255) / 256, 256>>>(N);
    sage_gemm_mma<<<148, GT, SMEM_TOTAL>>>(agg, emb, W1l, b1, W1r, N);

    // Layer 2: scalar scatter + fold + predict
    scatter2_kernel<<<(E + 255) / 256, 256>>>(src, dst, E);
    fold_kernel<<<(N + 255) / 256, 256>>>(N);
    predict_kernel<<<(L + 255) / 256, 256>>>(ls, ld, out, L);
}